// round 3
// baseline (speedup 1.0000x reference)
#include <cuda_runtime.h>

// Scratch (device globals — no allocation allowed)
__device__ float g_qkv[1024 * 1536];   // [B*N][3C] : qkv projection output
__device__ float g_att[1024 * 512];    // [B*N][C]  : attention output (pre-proj)

// ---------------------------------------------------------------------------
// GEMM: C[M][N] = A[M][K] @ B[N][K]^T (+ bias[N])
// Both A and B are K-major (row-major with K contiguous) — matches
// einsum('bnc,kc->bnk') and einsum('bnc,oc->bno').
// BM=BN=64, BK=16, 256 threads, 4x4 per thread.
// ---------------------------------------------------------------------------
template<bool HAS_BIAS>
__global__ __launch_bounds__(256) void gemm_kt(
    const float* __restrict__ A, const float* __restrict__ B,
    const float* __restrict__ bias, float* __restrict__ C,
    int M, int N, int K)
{
    const int BM = 64, BN = 64, BK = 16;
    __shared__ float As[BK][BM + 1];   // transposed tile, +1 pad (conflict-free)
    __shared__ float Bs[BK][BN + 4];   // +4 pad keeps 16B alignment for float4

    int tid = threadIdx.x;
    int tx = tid & 15;    // 16 thread-cols
    int ty = tid >> 4;    // 16 thread-rows
    int row0 = blockIdx.y * BM;
    int col0 = blockIdx.x * BN;

    float acc[4][4] = {};

    int lm = tid >> 2;          // 0..63 : tile row/col for loads
    int lk = (tid & 3) * 4;     // 0,4,8,12 : k offset (float4)

    const float* Ap = A + (size_t)(row0 + lm) * K + lk;
    const float* Bp = B + (size_t)(col0 + lm) * K + lk;

    for (int k0 = 0; k0 < K; k0 += BK) {
        float4 a4 = *(const float4*)(Ap + k0);
        float4 b4 = *(const float4*)(Bp + k0);
        As[lk + 0][lm] = a4.x; As[lk + 1][lm] = a4.y;
        As[lk + 2][lm] = a4.z; As[lk + 3][lm] = a4.w;
        Bs[lk + 0][lm] = b4.x; Bs[lk + 1][lm] = b4.y;
        Bs[lk + 2][lm] = b4.z; Bs[lk + 3][lm] = b4.w;
        __syncthreads();

        #pragma unroll
        for (int k = 0; k < BK; k++) {
            float af[4];
            #pragma unroll
            for (int i = 0; i < 4; i++) af[i] = As[k][ty * 4 + i];  // broadcast
            float4 bb = *(const float4*)&Bs[k][tx * 4];
            float bf[4] = {bb.x, bb.y, bb.z, bb.w};
            #pragma unroll
            for (int i = 0; i < 4; i++)
                #pragma unroll
                for (int j = 0; j < 4; j++)
                    acc[i][j] = fmaf(af[i], bf[j], acc[i][j]);
        }
        __syncthreads();
    }

    int c = col0 + tx * 4;
    float4 bv = make_float4(0.f, 0.f, 0.f, 0.f);
    if (HAS_BIAS) bv = *(const float4*)&bias[c];
    #pragma unroll
    for (int i = 0; i < 4; i++) {
        int r = row0 + ty * 4 + i;
        float4 o;
        o.x = acc[i][0] + bv.x;
        o.y = acc[i][1] + bv.y;
        o.z = acc[i][2] + bv.z;
        o.w = acc[i][3] + bv.w;
        *(float4*)&C[(size_t)r * N + c] = o;
    }
}

// ---------------------------------------------------------------------------
// Fourier attention core.
// Grid: (4 q-tiles of 64, B*H=32). Block: 256 threads.
// Thread t: query q = t&63 (within tile), k-subrange sub = t>>6 (64 keys each).
// score(q,k) = R^64 * prod_{chunks c of 16 dims} [prod sin(u) / prod u],
//   u = R*(q_d - k_d).  a4 = score^4.  out = (sum_k a4*v) / (sum_k a4 + eps).
// K (stored as -R*k) and V staged in dynamic smem (128KB). q (R-scaled) in regs.
// 4 partial results per query combined via smem reduction (smem reused).
// ---------------------------------------------------------------------------
__global__ __launch_bounds__(256, 1) void attn_kernel(
    const float* __restrict__ qkv, const float* __restrict__ paramR,
    float* __restrict__ outp)
{
    extern __shared__ float sm[];
    float* kS = sm;               // [256][64] : -R * k
    float* vS = sm + 256 * 64;    // [256][64] : v

    int tid = threadIdx.x;
    int bh = blockIdx.y;
    int b = bh >> 3;
    int h = bh & 7;
    int qbase = blockIdx.x * 64;
    float R = paramR[0];

    // qkv layout: [(b*256+n)][1536] with col = s*512 + h*64 + d
    const float* base = qkv + (size_t)(b * 256) * 1536 + h * 64;

    // Cooperative load of K (negated & scaled) and V tiles
    for (int i = tid; i < 256 * 16; i += 256) {
        int n = i >> 4;
        int d4 = (i & 15) << 2;
        float4 kv = *(const float4*)(base + (size_t)n * 1536 + 512 + d4);
        float4 ks;
        ks.x = -R * kv.x; ks.y = -R * kv.y; ks.z = -R * kv.z; ks.w = -R * kv.w;
        *(float4*)&kS[n * 64 + d4] = ks;
        *(float4*)&vS[n * 64 + d4] = *(const float4*)(base + (size_t)n * 1536 + 1024 + d4);
    }

    int q = tid & 63;
    int sub = tid >> 6;

    // q row, scaled by R, in registers
    float qr[64];
    {
        const float* qp = base + (size_t)(qbase + q) * 1536;
        #pragma unroll
        for (int d = 0; d < 64; d += 4) {
            float4 t = *(const float4*)(qp + d);
            qr[d + 0] = R * t.x; qr[d + 1] = R * t.y;
            qr[d + 2] = R * t.z; qr[d + 3] = R * t.w;
        }
    }
    float R64;
    { float p = R; p *= p; p *= p; p *= p; p *= p; p *= p; p *= p; R64 = p; }  // R^64

    __syncthreads();

    float acc[64];
    #pragma unroll
    for (int d = 0; d < 64; d++) acc[d] = 0.f;
    float sumA = 0.f;

    const int kstart = sub * 64;
    for (int kk = kstart; kk < kstart + 64; kk++) {
        const float4* kp4 = (const float4*)&kS[kk * 64];
        float sc = R64;
        #pragma unroll
        for (int c = 0; c < 4; c++) {
            float pn = 1.f, pd = 1.f;
            #pragma unroll
            for (int j = 0; j < 4; j++) {
                float4 kv = kp4[c * 4 + j];
                int dd = c * 16 + j * 4;
                float u0 = qr[dd + 0] + kv.x;   // = R*(q-k)
                float u1 = qr[dd + 1] + kv.y;
                float u2 = qr[dd + 2] + kv.z;
                float u3 = qr[dd + 3] + kv.w;
                float s0 = __sinf(u0), s1 = __sinf(u1);
                float s2 = __sinf(u2), s3 = __sinf(u3);
                // exact-zero guard (avoids 0/0; matches reference near0 -> R)
                if (u0 == 0.f) { s0 = 1.f; u0 = 1.f; }
                if (u1 == 0.f) { s1 = 1.f; u1 = 1.f; }
                if (u2 == 0.f) { s2 = 1.f; u2 = 1.f; }
                if (u3 == 0.f) { s3 = 1.f; u3 = 1.f; }
                pn *= s0 * s1;  pd *= u0 * u1;
                pn *= s2 * s3;  pd *= u2 * u3;
            }
            sc *= __fdividef(pn, pd);
        }
        float a2 = sc * sc;
        float a4 = a2 * a2;
        sumA += a4;
        const float4* vp4 = (const float4*)&vS[kk * 64];
        #pragma unroll
        for (int j = 0; j < 16; j++) {
            float4 vv = vp4[j];
            acc[j * 4 + 0] = fmaf(a4, vv.x, acc[j * 4 + 0]);
            acc[j * 4 + 1] = fmaf(a4, vv.y, acc[j * 4 + 1]);
            acc[j * 4 + 2] = fmaf(a4, vv.z, acc[j * 4 + 2]);
            acc[j * 4 + 3] = fmaf(a4, vv.w, acc[j * 4 + 3]);
        }
    }

    __syncthreads();   // everyone done reading kS/vS — safe to reuse smem

    // Stage partials: red[sub][q][0..63]=acc, [64]=sumA (stride 65: conflict-free)
    float* red = sm;
    {
        float* rp = red + (sub * 64 + q) * 65;
        #pragma unroll
        for (int d = 0; d < 64; d++) rp[d] = acc[d];
        rp[64] = sumA;
    }
    __syncthreads();

    // Combine 4 partials per query, normalize, write out [b*256+n][h*64+d]
    {
        int q2 = tid & 63;
        int part = tid >> 6;
        const float* r0 = red + q2 * 65;
        const float* r1 = red + (64 + q2) * 65;
        const float* r2 = red + (128 + q2) * 65;
        const float* r3 = red + (192 + q2) * 65;
        float stot = r0[64] + r1[64] + r2[64] + r3[64];
        float inv = __fdividef(1.0f, stot + 1e-6f);
        float* dst = outp + (size_t)(b * 256 + qbase + q2) * 512 + h * 64;
        #pragma unroll
        for (int d = part * 16; d < part * 16 + 16; d++) {
            dst[d] = (r0[d] + r1[d] + r2[d] + r3[d]) * inv;
        }
    }
}

// ---------------------------------------------------------------------------
extern "C" void kernel_launch(void* const* d_in, const int* in_sizes, int n_in,
                              void* d_out, int out_size)
{
    const float* x      = (const float*)d_in[0];   // (4,256,512)
    const float* w_qkv  = (const float*)d_in[1];   // (1536,512)
    const float* w_proj = (const float*)d_in[2];   // (512,512)
    const float* b_proj = (const float*)d_in[3];   // (512,)
    const float* paramR = (const float*)d_in[4];   // (1,)
    float* out = (float*)d_out;                    // (4,256,512)

    float *qkv, *att;
    cudaGetSymbolAddress((void**)&qkv, g_qkv);
    cudaGetSymbolAddress((void**)&att, g_att);

    cudaFuncSetAttribute(attn_kernel,
                         cudaFuncAttributeMaxDynamicSharedMemorySize, 131072);

    dim3 thr(256);
    // 1) QKV projection: [1024][1536] = x[1024][512] @ w_qkv[1536][512]^T
    gemm_kt<false><<<dim3(1536 / 64, 1024 / 64), thr>>>(
        x, w_qkv, nullptr, qkv, 1024, 1536, 512);

    // 2) Fourier attention: grid (q-tiles=4, b*h=32), 128KB smem
    attn_kernel<<<dim3(4, 32), thr, 131072>>>(qkv, paramR, att);

    // 3) Output projection + bias: [1024][512] = att @ w_proj^T + b_proj
    gemm_kt<true><<<dim3(512 / 64, 1024 / 64), thr>>>(
        att, w_proj, b_proj, out, 1024, 512, 512);
}